// round 16
// baseline (speedup 1.0000x reference)
#include <cuda_runtime.h>
#include <cstdint>

// ---------------------------------------------------------------------------
// LaneAttention: per-lane MLP score -> per-group(8) softmax -> weighted pool
// M = 262144 lanes, groups of 8 contiguous lanes, N = 32768, out [N,192]
//
// R16: single-wave persistent grid. grid=1024 CTAs (TPB=128, 7 CTAs/SM -> all
// resident in one wave); each CTA processes 2 tiles of 128 rows. Tile-1's
// first two staging chunks are issued during tile-0's last MLP chunks, so the
// DRAM fetches fly under tile-0's phase-2 pooling — the phase2->phase1 seam
// (formerly the wave boundary) is overlapped instead of serialized.
// Body = R14: warp-private double-buffered cp.async staging, weights in the
// constant bank, zero block barriers, warp-local phase 2 from L2, __ldcs fut.
// ---------------------------------------------------------------------------

static constexpr int TPB = 128;        // 4 warps, 32 rows per warp
static constexpr int NT  = 2;          // tiles per CTA
static constexpr int CS  = 5;          // buffer row stride in float4 (4 data + 1 pad)
static constexpr int WBUF_F4 = 32 * CS;              // 160 float4 per warp-buffer

__constant__ float cW1[128 * 16];      // 8 KB

__device__ __forceinline__ unsigned long long pack_dup(float x) {
    unsigned long long r;
    asm("mov.b64 %0, {%1, %1};" : "=l"(r) : "f"(x));
    return r;
}
__device__ __forceinline__ unsigned long long pack_xy(float x, float y) {
    unsigned long long r;
    asm("mov.b64 %0, {%1, %2};" : "=l"(r) : "f"(x), "f"(y));
    return r;
}
__device__ __forceinline__ void ffma2(unsigned long long &d, unsigned long long a, unsigned long long b) {
    asm("fma.rn.f32x2 %0, %1, %2, %0;" : "+l"(d) : "l"(a), "l"(b));
}
__device__ __forceinline__ float2 unpack2(unsigned long long v) {
    float2 f;
    asm("mov.b64 {%0, %1}, %2;" : "=f"(f.x), "=f"(f.y) : "l"(v));
    return f;
}
__device__ __forceinline__ void cp_async16(uint32_t dst_smem, const void* src) {
    asm volatile("cp.async.cg.shared.global [%0], [%1], 16;\n"
                 :: "r"(dst_smem), "l"(src) : "memory");
}
__device__ __forceinline__ void cp_commit() {
    asm volatile("cp.async.commit_group;\n");
}
template <int N>
__device__ __forceinline__ void cp_wait() {
    asm volatile("cp.async.wait_group %0;\n" :: "n"(N) : "memory");
}

extern __shared__ float smem_f[];
// layout (floats): xbuf 4 warps * 2 bufs * 160 f4 = 1280 f4 = 5120 floats
//                  probs 128 | outrow 16 ints
static constexpr int PROBS_OFF  = 2 * 4 * WBUF_F4 * 4;              // 5120
static constexpr int SMEM_BYTES = (PROBS_OFF + TPB) * 4 + 128;      // ~21.1 KB

// stage 16 columns (4 float4) of THIS WARP's 32 rows of `arr` into its buffer b
__device__ __forceinline__ void stage_chunk_w(const float* arr, int wrow0, int cc,
                                              int b, int lane, uint32_t wbase_s)
{
    const float4* src = (const float4*)(arr + (size_t)wrow0 * 64) + (cc & 3) * 4;
    #pragma unroll
    for (int u = 0; u < 4; ++u) {
        int f = lane + 32 * u;          // flat float4 idx 0..127 within the warp tile
        int r = f >> 2, c = f & 3;      // r = warp-local row 0..31
        cp_async16(wbase_s + (uint32_t)(b * WBUF_F4 + r * CS + c) * 16u,
                   src + r * 16 + c);
    }
    cp_commit();
}

__global__ __launch_bounds__(TPB, 7)
void lane_attn_kernel(const float* __restrict__ ht,
                      const float* __restrict__ info,
                      const float* __restrict__ fut,
                      const float* __restrict__ b1,   // [16]
                      const float* __restrict__ W2,   // [16]
                      const float* __restrict__ b2,   // [1]
                      const int*   __restrict__ seg,  // [M]
                      float* __restrict__ out,        // [N,192]
                      int tile_rows)                  // rows per tile step = grid*TPB
{
    float*  probs  = smem_f + PROBS_OFF;
    int*    outrow = (int*)(probs + TPB);
    const float4* xbuf4 = (const float4*)smem_f;

    const int tid   = threadIdx.x;
    const int wrp   = tid >> 5;
    const int lane  = tid & 31;
    const int wofs  = wrp * 2 * WBUF_F4;             // this warp's buffer base (f4)
    const uint32_t wbase_s = (uint32_t)__cvta_generic_to_shared(smem_f)
                           + (uint32_t)wofs * 16u;

    const int row0_0  = blockIdx.x * TPB;            // tile 0 base row
    const int wrow0_0 = row0_0 + wrp * 32;

    // prime the pipeline for tile 0: chunks 0,1 in flight
    stage_chunk_w(ht, wrow0_0, 0, 0, lane, wbase_s);
    stage_chunk_w(ht, wrow0_0, 1, 1, lane, wbase_s);

    unsigned long long bias[8];
    {
        const float2* b12 = (const float2*)b1;
        #pragma unroll
        for (int j = 0; j < 8; ++j) {
            float2 bv = b12[j];
            bias[j] = pack_xy(bv.x, bv.y);
        }
    }
    const float b2v = b2[0];

    for (int t = 0; t < NT; ++t) {
        const int row0  = row0_0 + t * tile_rows;
        const int wrow0 = row0 + wrp * 32;
        const bool last = (t == NT - 1);

        // per-warp group->output-row ids for this tile (warp-local)
        if (lane < 4)
            outrow[wrp * 4 + lane] = seg[wrow0 + lane * 8];

        unsigned long long hp[8];
        #pragma unroll
        for (int j = 0; j < 8; ++j) hp[j] = bias[j];

        // ---- phase 1: 8 chunks (4 ht + 4 info), warp-private double buffer --
        #pragma unroll
        for (int cc = 0; cc < 8; ++cc) {
            if (last && cc == 7) cp_wait<0>(); else cp_wait<1>();
            __syncwarp();                     // publish lanes' copies warp-wide

            const int b = cc & 1;
            const float4* xb = xbuf4 + wofs + b * WBUF_F4 + lane * CS;
            #pragma unroll
            for (int q2 = 0; q2 < 4; ++q2) {
                float4 v = xb[q2];
                float xs[4] = {v.x, v.y, v.z, v.w};
                #pragma unroll
                for (int c = 0; c < 4; ++c) {
                    const int k = cc * 16 + q2 * 4 + c;   // weight row, compile-time
                    unsigned long long xv = pack_dup(xs[c]);
                    const double2* wr = (const double2*)(cW1 + k * 16);
                    double2 w01 = wr[0];
                    double2 w23 = wr[1];
                    ffma2(hp[0], xv, __double_as_longlong(w01.x));
                    ffma2(hp[1], xv, __double_as_longlong(w01.y));
                    ffma2(hp[2], xv, __double_as_longlong(w23.x));
                    ffma2(hp[3], xv, __double_as_longlong(w23.y));
                    double2 w45 = wr[2];
                    double2 w67 = wr[3];
                    ffma2(hp[4], xv, __double_as_longlong(w45.x));
                    ffma2(hp[5], xv, __double_as_longlong(w45.y));
                    ffma2(hp[6], xv, __double_as_longlong(w67.x));
                    ffma2(hp[7], xv, __double_as_longlong(w67.y));
                }
            }
            __syncwarp();                     // all lanes done reading buffer b
            // refill the buffer just consumed:
            //   cc<6  -> this tile's chunk cc+2
            //   cc>=6 -> NEXT tile's chunk cc-6 (flies under this tile's phase 2)
            if (cc < 6) {
                stage_chunk_w(cc + 2 < 4 ? ht : info, wrow0, cc + 2, cc & 1,
                              lane, wbase_s);
            } else if (!last) {
                stage_chunk_w(ht, wrow0 + tile_rows, cc - 6, cc & 1,
                              lane, wbase_s);
            }
        }

        // ReLU + second layer -> score
        float score = b2v;
        #pragma unroll
        for (int j = 0; j < 8; ++j) {
            float2 h2 = unpack2(hp[j]);
            score += fmaxf(h2.x, 0.f) * W2[2 * j]
                   + fmaxf(h2.y, 0.f) * W2[2 * j + 1];
        }

        // ---- group-of-8 softmax (warp-aligned groups) ------------------------
        float m = score;
        #pragma unroll
        for (int d = 1; d < 8; d <<= 1)
            m = fmaxf(m, __shfl_xor_sync(0xffffffffu, m, d));
        float e = __expf(score - m);
        float s = e;
        #pragma unroll
        for (int d = 1; d < 8; d <<= 1)
            s += __shfl_xor_sync(0xffffffffu, s, d);
        probs[tid] = e / s;

        __syncwarp();   // phase 2 is warp-local: own rows, own probs, own outrow

        // ---- phase 2: weighted pooling, float4 per lane (ht/info from L2) ----
        const int h = (tid >> 4) & 1;
        const int k = tid & 15;

        #pragma unroll
        for (int it = 0; it < 2; ++it) {
            const int gloc  = wrp * 4 + it * 2 + h;      // local group 0..15
            const int lbase = gloc * 8;
            const float4* hb = (const float4*)(ht   + (size_t)(row0 + lbase) * 64);
            const float4* ib = (const float4*)(info + (size_t)(row0 + lbase) * 64);
            const float4* fb = (const float4*)(fut  + (size_t)(row0 + lbase) * 64);

            float4 ah = make_float4(0.f, 0.f, 0.f, 0.f);
            float4 ai = ah, af = ah;
            #pragma unroll
            for (int j = 0; j < 8; ++j) {
                const float p = probs[lbase + j];
                float4 hv = hb[j * 16 + k];               // L2 hit (phase-1 resident)
                float4 iv = ib[j * 16 + k];               // L2 hit
                float4 fv = __ldcs(fb + j * 16 + k);      // single-use stream
                ah.x += p * hv.x; ah.y += p * hv.y; ah.z += p * hv.z; ah.w += p * hv.w;
                ai.x += p * iv.x; ai.y += p * iv.y; ai.z += p * iv.z; ai.w += p * iv.w;
                af.x += p * fv.x; af.y += p * fv.y; af.z += p * fv.z; af.w += p * fv.w;
            }
            float4* o4 = (float4*)(out + (size_t)outrow[gloc] * 192);
            o4[k]      = ah;
            o4[16 + k] = ai;
            o4[32 + k] = af;
        }
        __syncwarp();   // warp done with this tile's probs/outrow before reuse
    }
}

extern "C" void kernel_launch(void* const* d_in, const int* in_sizes, int n_in,
                              void* d_out, int out_size)
{
    const float* ht   = (const float*)d_in[0];
    const float* info = (const float*)d_in[1];
    const float* fut  = (const float*)d_in[2];
    const float* W1   = (const float*)d_in[3];
    const float* b1   = (const float*)d_in[4];
    const float* W2   = (const float*)d_in[5];
    const float* b2   = (const float*)d_in[6];
    const int*   seg  = (const int*)d_in[7];
    float* out = (float*)d_out;

    const int M = in_sizes[0] / 64;          // 262144
    const int nblocks  = M / (TPB * NT);     // 1024 — single resident wave
    const int tile_rows = nblocks * TPB;     // 131072 rows between a CTA's tiles

    static void* cw1_addr = nullptr;
    if (!cw1_addr) {
        cudaGetSymbolAddress(&cw1_addr, cW1);
        cudaFuncSetAttribute(lane_attn_kernel,
                             cudaFuncAttributeMaxDynamicSharedMemorySize, SMEM_BYTES);
    }

    // D2D async copy into the constant bank — one graph memcpy node
    cudaMemcpyAsync(cw1_addr, W1, 128 * 16 * sizeof(float), cudaMemcpyDeviceToDevice);

    lane_attn_kernel<<<nblocks, TPB, SMEM_BYTES>>>(ht, info, fut, b1, W2, b2, seg,
                                                   out, tile_rows);
}